// round 13
// baseline (speedup 1.0000x reference)
#include <cuda_runtime.h>
#include <cstdint>
#include <cstddef>

// Problem constants (fixed by the reference)
#define RN 6
#define NN 50000
#define EE 200000
#define DD 768
#define HC 256      // H*C
#define OO 64

// ---------------------------------------------------------------------------
// Scratch layout (floats) — intermediates duplicated per relation parity
// ---------------------------------------------------------------------------
__device__ float g_scratch[136955904];

#define OFF_XLR0  0u
#define OFF_XLR1  25600000u
#define OFF_H0    51200000u
#define OFF_H1P   64000000u     // H parity 1
#define OFF_H1_0  76800000u
#define OFF_H1_1  80000000u
#define OFF_P1_0  83200000u
#define OFF_P1_1  86400000u
#define OFF_P2_0  89600000u
#define OFF_P2_1  92800000u
#define OFF_XR    96000000u
#define OFF_WT    134400000u
#define OFF_WB1   136759296u

// CSR structures (ints)
#define CHUNKS 49   // ceil(NN / 1024)
__device__ int g_rowptr[RN * (NN + 1)];
__device__ int g_colidx[RN * EE];
__device__ int g_tmp[2 * RN * NN];        // counts | cursor
__device__ int g_blksum[RN * CHUNKS];

// ===========================================================================
// PTX helpers (plain-sm_103-legal: cp.async, ldmatrix, mma.sync)
// ===========================================================================
__device__ __forceinline__ uint32_t smem_u32(const void* p) {
    uint32_t a;
    asm("{ .reg .u64 t; cvta.to.shared.u64 t, %1; cvt.u32.u64 %0, t; }"
        : "=r"(a) : "l"(p));
    return a;
}
__device__ __forceinline__ void cp16(uint32_t dst, const void* src, uint32_t sz) {
    asm volatile("cp.async.cg.shared.global [%0], [%1], 16, %2;"
                 :: "r"(dst), "l"(src), "r"(sz) : "memory");
}
__device__ __forceinline__ void cp_commit() {
    asm volatile("cp.async.commit_group;" ::: "memory");
}
__device__ __forceinline__ void cp_wait1() {
    asm volatile("cp.async.wait_group 1;" ::: "memory");
}
__device__ __forceinline__ void cp_wait2() {
    asm volatile("cp.async.wait_group 2;" ::: "memory");
}
#define LDSM4(r0, r1, r2, r3, addr) \
    asm volatile("ldmatrix.sync.aligned.m8n8.x4.shared.b16 {%0,%1,%2,%3}, [%4];" \
                 : "=r"(r0), "=r"(r1), "=r"(r2), "=r"(r3) : "r"(addr))

#define MMA_TF32(d, a, b0, b1) \
    asm volatile("mma.sync.aligned.m16n8k8.row.col.f32.tf32.tf32.f32 " \
                 "{%0,%1,%2,%3}, {%4,%5,%6,%7}, {%8,%9}, {%0,%1,%2,%3};" \
                 : "+f"((d)[0]), "+f"((d)[1]), "+f"((d)[2]), "+f"((d)[3]) \
                 : "r"((a)[0]), "r"((a)[1]), "r"((a)[2]), "r"((a)[3]), \
                   "r"(b0), "r"(b1))

// ===========================================================================
// Preprocessing: tf32 rounding + weight transposes
// ===========================================================================
__device__ __forceinline__ float rna_tf32(float v) {
    uint32_t o;
    asm("cvt.rna.tf32.f32 %0, %1;" : "=r"(o) : "f"(v));
    return __uint_as_float(o);
}

__global__ void round_tf32_kernel(const float4* __restrict__ in, float4* __restrict__ out, int n4) {
    int i = blockIdx.x * blockDim.x + threadIdx.x;
    int stride = gridDim.x * blockDim.x;
    for (; i < n4; i += stride) {
        float4 v = in[i];
        v.x = rna_tf32(v.x); v.y = rna_tf32(v.y);
        v.z = rna_tf32(v.z); v.w = rna_tf32(v.w);
        out[i] = v;
    }
}

// WT[r][n][k] = rna(Wl[r][k][n]) for n<256 else rna(Wr[r][k][n-256])
__global__ void transpose_w_kernel(const float* __restrict__ Wl, const float* __restrict__ Wr,
                                   float* __restrict__ WT) {
    __shared__ float tile[32][33];
    int r = blockIdx.z;
    int k0 = blockIdx.x * 32;
    int n0 = blockIdx.y * 32;
    const float* W = (n0 < 256) ? Wl : Wr;
    int nc0 = (n0 < 256) ? n0 : (n0 - 256);
    int tx = threadIdx.x, ty = threadIdx.y;  // 32 x 8
#pragma unroll
    for (int i = 0; i < 32; i += 8) {
        float v = W[((size_t)r * DD + k0 + ty + i) * HC + nc0 + tx];
        tile[ty + i][tx] = rna_tf32(v);
    }
    __syncthreads();
#pragma unroll
    for (int i = 0; i < 32; i += 8) {
        WT[((size_t)r * 512 + n0 + ty + i) * DD + k0 + tx] = tile[tx][ty + i];
    }
}

// WB1[r][n][k] = rna(Wrel1[r][k][n]) for n<64 else rna(Wroot1[r][k][n-64]); K=256
__global__ void transpose_wb1_kernel(const float* __restrict__ Wrel1,
                                     const float* __restrict__ Wroot1,
                                     float* __restrict__ WB1) {
    __shared__ float tile[32][33];
    int r = blockIdx.z;
    int k0 = blockIdx.x * 32;
    int n0 = blockIdx.y * 32;
    const float* W = (n0 < 64) ? Wrel1 : Wroot1;
    int nc0 = (n0 < 64) ? n0 : (n0 - 64);
    int tx = threadIdx.x, ty = threadIdx.y;  // 32 x 8
#pragma unroll
    for (int i = 0; i < 32; i += 8) {
        float v = W[((size_t)r * HC + k0 + ty + i) * OO + nc0 + tx];
        tile[ty + i][tx] = rna_tf32(v);
    }
    __syncthreads();
#pragma unroll
    for (int i = 0; i < 32; i += 8) {
        WB1[((size_t)r * 128 + n0 + ty + i) * HC + k0 + tx] = tile[tx][ty + i];
    }
}

// ===========================================================================
// CSR build: zero -> histogram -> 3-phase parallel scan -> fill
// ===========================================================================
__global__ void zero_int_kernel(int* p, int n) {
    int i = blockIdx.x * blockDim.x + threadIdx.x;
    int stride = gridDim.x * blockDim.x;
    for (; i < n; i += stride) p[i] = 0;
}

__global__ void hist_kernel(const int* __restrict__ ei, int* __restrict__ counts) {
    int i = blockIdx.x * blockDim.x + threadIdx.x;
    if (i >= RN * EE) return;
    int r = i / EE, e = i - r * EE;
    int t = ei[(size_t)r * 2 * EE + EE + e];
    atomicAdd(&counts[r * NN + t], 1);
}

__global__ void blocksum_kernel(const int* __restrict__ counts, int* __restrict__ blksum) {
    __shared__ int sred[256];
    int r = blockIdx.y;
    int c0 = blockIdx.x * 1024;
    const int* c = counts + r * NN;
    int s = 0;
#pragma unroll
    for (int k = 0; k < 4; k++) {
        int i = c0 + threadIdx.x + k * 256;
        if (i < NN) s += c[i];
    }
    sred[threadIdx.x] = s;
    __syncthreads();
    for (int off = 128; off > 0; off >>= 1) {
        if (threadIdx.x < off) sred[threadIdx.x] += sred[threadIdx.x + off];
        __syncthreads();
    }
    if (threadIdx.x == 0) blksum[r * CHUNKS + blockIdx.x] = sred[0];
}

__global__ void blkscan_kernel(int* __restrict__ blksum) {
    int r = blockIdx.x;
    if (threadIdx.x == 0) {
        int acc = 0;
        for (int i = 0; i < CHUNKS; i++) {
            int v = blksum[r * CHUNKS + i];
            blksum[r * CHUNKS + i] = acc;
            acc += v;
        }
    }
}

__global__ void __launch_bounds__(1024)
chunkscan_kernel(const int* __restrict__ counts, const int* __restrict__ blksum,
                 int* __restrict__ rowptr) {
    __shared__ int sdata[1024];
    int r = blockIdx.y;
    int i = blockIdx.x * 1024 + threadIdx.x;
    const int* c = counts + r * NN;
    int v = (i < NN) ? c[i] : 0;
    sdata[threadIdx.x] = v;
    __syncthreads();
#pragma unroll
    for (int off = 1; off < 1024; off <<= 1) {
        int tv = (threadIdx.x >= off) ? sdata[threadIdx.x - off] : 0;
        __syncthreads();
        sdata[threadIdx.x] += tv;
        __syncthreads();
    }
    int* rp = rowptr + r * (NN + 1);
    int offc = blksum[r * CHUNKS + blockIdx.x];
    if (i < NN) rp[i + 1] = offc + sdata[threadIdx.x];
    if (i == 0) rp[0] = 0;
}

__global__ void fillcsr_kernel(const int* __restrict__ ei, const int* __restrict__ rowptr,
                               int* __restrict__ cursor, int* __restrict__ colidx) {
    int i = blockIdx.x * blockDim.x + threadIdx.x;
    if (i >= RN * EE) return;
    int r = i / EE, e = i - r * EE;
    int s = ei[(size_t)r * 2 * EE + e];
    int t = ei[(size_t)r * 2 * EE + EE + e];
    int pos = rowptr[r * (NN + 1) + t] + atomicAdd(&cursor[r * NN + t], 1);
    colidx[r * EE + pos] = s;
}

// ===========================================================================
// Big tf32 GEMM: BM=128 BN=256 BK=32, 512 threads (16 warps, 2m x 8n),
// warp tile 64x32, 3-stage cp.async. C[M][512] tile = A @ B^T. (proven R11)
// ===========================================================================
#define GBM 128
#define GBN 256
#define GBK 32
#define GST 3
#define A_TB (GBM * GBK * 4)      // 16384
#define B_TB (GBN * GBK * 4)      // 32768
#define KIT24 24
#define SMEM_BIG (GST * (A_TB + B_TB) + 1024)   // 148480

__global__ void __launch_bounds__(512, 1)
gemm_big_kernel(const float* __restrict__ A, const float* __restrict__ B,
                float* __restrict__ C, int M) {
    extern __shared__ char sm_raw[];
    uint32_t smbase = (smem_u32(sm_raw) + 1023u) & ~1023u;
    uint32_t sA = smbase;                    // 3 x 16KB
    uint32_t sB = smbase + GST * A_TB;       // 3 x 32KB

    const int K = DD;
    int tid = threadIdx.x;
    int lane = tid & 31, wid = tid >> 5;     // 16 warps
    int wm = wid & 1, wn = wid >> 1;         // 2 x 8
    int M0 = blockIdx.y * GBM, N0 = blockIdx.x * GBN;

    uint32_t dstA[2]; const float* srcA[2]; uint32_t szA[2];
#pragma unroll
    for (int i = 0; i < 2; i++) {
        int lin = tid + i * 512;
        int row = lin >> 3, ch = lin & 7;
        dstA[i] = row * 128 + ((ch * 16) ^ ((row & 7) * 16));
        int ga = M0 + row;
        szA[i] = (ga < M) ? 16u : 0u;
        srcA[i] = A + (size_t)(ga < M ? ga : 0) * K + ch * 4;
    }
    uint32_t dstB[4]; const float* srcB[4];
#pragma unroll
    for (int i = 0; i < 4; i++) {
        int lin = tid + i * 512;
        int row = lin >> 3, ch = lin & 7;    // row 0..255
        dstB[i] = row * 128 + ((ch * 16) ^ ((row & 7) * 16));
        srcB[i] = B + (size_t)(N0 + row) * K + ch * 4;
    }

    uint32_t aOff[4], bOff[2];
#pragma unroll
    for (int mt = 0; mt < 4; mt++) {
        int rowA = wm * 64 + mt * 16 + (lane & 7) + ((lane >> 3) & 1) * 8;
        uint32_t q = (uint32_t)(((lane >> 4) * 16) ^ ((rowA & 7) * 16));
        aOff[mt] = (uint32_t)rowA * 128 + q;
    }
#pragma unroll
    for (int bp = 0; bp < 2; bp++) {
        int rowB = wn * 32 + bp * 16 + (lane & 7) + ((lane >> 4) & 1) * 8;
        uint32_t q = (uint32_t)((((lane >> 3) & 1) * 16) ^ ((rowB & 7) * 16));
        bOff[bp] = (uint32_t)rowB * 128 + q;
    }

    float acc[4][4][4];
#pragma unroll
    for (int mt = 0; mt < 4; mt++)
#pragma unroll
        for (int nt = 0; nt < 4; nt++)
#pragma unroll
            for (int j = 0; j < 4; j++) acc[mt][nt][j] = 0.f;

#define FILL_STAGE(st, k0)                                          \
    do {                                                            \
        _Pragma("unroll")                                           \
        for (int i = 0; i < 2; i++)                                 \
            cp16(sA + (st) * A_TB + dstA[i], srcA[i] + (k0), szA[i]); \
        _Pragma("unroll")                                           \
        for (int i = 0; i < 4; i++)                                 \
            cp16(sB + (st) * B_TB + dstB[i], srcB[i] + (k0), 16u);  \
    } while (0)

    FILL_STAGE(0, 0);
    cp_commit();
    FILL_STAGE(1, GBK);
    cp_commit();

    for (int it = 0; it < KIT24; it++) {
        cp_wait1();
        __syncthreads();

        int nx = it + 2;
        if (nx < KIT24) {
            int s2 = nx % GST;
            FILL_STAGE(s2, nx * GBK);
        }
        cp_commit();

        int s = it % GST;
        uint32_t baseA = sA + s * A_TB;
        uint32_t baseB = sB + s * B_TB;

#pragma unroll
        for (int ks = 0; ks < 4; ks++) {
            uint32_t x = (uint32_t)(ks * 32);
            uint32_t afr[4][4];
            uint32_t bfr[4][2];
#pragma unroll
            for (int mt = 0; mt < 4; mt++)
                LDSM4(afr[mt][0], afr[mt][1], afr[mt][2], afr[mt][3],
                      baseA + (aOff[mt] ^ x));
#pragma unroll
            for (int bp = 0; bp < 2; bp++) {
                uint32_t r0, r1, r2, r3;
                LDSM4(r0, r1, r2, r3, baseB + (bOff[bp] ^ x));
                bfr[2 * bp][0] = r0;     bfr[2 * bp][1] = r1;
                bfr[2 * bp + 1][0] = r2; bfr[2 * bp + 1][1] = r3;
            }
#pragma unroll
            for (int mt = 0; mt < 4; mt++)
#pragma unroll
                for (int nt = 0; nt < 4; nt++)
                    MMA_TF32(acc[mt][nt], afr[mt], bfr[nt][0], bfr[nt][1]);
        }
    }
#undef FILL_STAGE

    int r = lane >> 2, c = (lane & 3) * 2;
#pragma unroll
    for (int mt = 0; mt < 4; mt++) {
        int grow = M0 + wm * 64 + mt * 16 + r;
#pragma unroll
        for (int nt = 0; nt < 4; nt++) {
            int gcol = N0 + wn * 32 + nt * 8 + c;
            if (grow < M)
                *(float2*)(C + (size_t)grow * 512 + gcol) =
                    make_float2(acc[mt][nt][0], acc[mt][nt][1]);
            if (grow + 8 < M)
                *(float2*)(C + (size_t)(grow + 8) * 512 + gcol) =
                    make_float2(acc[mt][nt][2], acc[mt][nt][3]);
        }
    }
}

// ===========================================================================
// DUAL tf32 GEMM (GraphConv-1) — proven version. BM=128 BN=128 BK=32,
// 4-stage, 256 threads, KITN=8, ks-double-buffered fragments.
// ===========================================================================
#define BM 128
#define BN 128
#define BK 32
#define GSTG 4
#define TILE_BYTES (BM * BK * 4)
#define SMEM_GEMM (GSTG * 2 * TILE_BYTES + 1024)

__global__ void __launch_bounds__(256, 1)
gemm_dual_kernel(const float* __restrict__ A, const float* __restrict__ B,
                 float* __restrict__ C, float* __restrict__ C2,
                 const float* __restrict__ bias, int M) {
    extern __shared__ char sm_raw[];
    uint32_t smbase = (smem_u32(sm_raw) + 1023u) & ~1023u;
    uint32_t sA = smbase;
    uint32_t sB = smbase + GSTG * TILE_BYTES;
    const int K = HC;
    const int KITN = 8;

    int tid = threadIdx.x;
    int lane = tid & 31, wid = tid >> 5;
    int wm = wid & 1, wn = wid >> 1;
    int M0 = blockIdx.y * BM;

    uint32_t dstOff[4];
    const float* srcA[4]; uint32_t szA[4];
    const float* srcB[4];
#pragma unroll
    for (int i = 0; i < 4; i++) {
        int lin = tid + i * 256;
        int row = lin >> 3, ch = lin & 7;
        dstOff[i] = row * 128 + ((ch * 16) ^ ((row & 7) * 16));
        int ga = M0 + row;
        szA[i] = (ga < M) ? 16u : 0u;
        srcA[i] = A + (size_t)(ga < M ? ga : 0) * K + ch * 4;
        srcB[i] = B + (size_t)row * K + ch * 4;
    }

    uint32_t aOff[4], bOff[2];
#pragma unroll
    for (int mt = 0; mt < 4; mt++) {
        int rowA = wm * 64 + mt * 16 + (lane & 7) + ((lane >> 3) & 1) * 8;
        uint32_t q = (uint32_t)(((lane >> 4) * 16) ^ ((rowA & 7) * 16));
        aOff[mt] = (uint32_t)rowA * 128 + q;
    }
#pragma unroll
    for (int bp = 0; bp < 2; bp++) {
        int rowB = wn * 32 + bp * 16 + (lane & 7) + ((lane >> 4) & 1) * 8;
        uint32_t q = (uint32_t)((((lane >> 3) & 1) * 16) ^ ((rowB & 7) * 16));
        bOff[bp] = (uint32_t)rowB * 128 + q;
    }

    float acc[4][4][4];
#pragma unroll
    for (int mt = 0; mt < 4; mt++)
#pragma unroll
        for (int nt = 0; nt < 4; nt++)
#pragma unroll
            for (int j = 0; j < 4; j++) acc[mt][nt][j] = 0.f;

#pragma unroll
    for (int s = 0; s < 3; s++) {
#pragma unroll
        for (int i = 0; i < 4; i++) {
            cp16(sA + s * TILE_BYTES + dstOff[i], srcA[i] + s * BK, szA[i]);
            cp16(sB + s * TILE_BYTES + dstOff[i], srcB[i] + s * BK, 16u);
        }
        cp_commit();
    }

    uint32_t afr[2][4][4];
    uint32_t bfr[2][4][2];

    for (int it = 0; it < KITN; it++) {
        cp_wait2();
        __syncthreads();

        int nx = it + 3;
        if (nx < KITN) {
            int s2 = nx % GSTG;
#pragma unroll
            for (int i = 0; i < 4; i++) {
                cp16(sA + s2 * TILE_BYTES + dstOff[i], srcA[i] + nx * BK, szA[i]);
                cp16(sB + s2 * TILE_BYTES + dstOff[i], srcB[i] + nx * BK, 16u);
            }
        }
        cp_commit();

        int s = it % GSTG;
        uint32_t baseA = sA + s * TILE_BYTES;
        uint32_t baseB = sB + s * TILE_BYTES;

#pragma unroll
        for (int mt = 0; mt < 4; mt++)
            LDSM4(afr[0][mt][0], afr[0][mt][1], afr[0][mt][2], afr[0][mt][3],
                  baseA + aOff[mt]);
#pragma unroll
        for (int bp = 0; bp < 2; bp++) {
            uint32_t r0, r1, r2, r3;
            LDSM4(r0, r1, r2, r3, baseB + bOff[bp]);
            bfr[0][2 * bp][0] = r0;     bfr[0][2 * bp][1] = r1;
            bfr[0][2 * bp + 1][0] = r2; bfr[0][2 * bp + 1][1] = r3;
        }

#pragma unroll
        for (int ks = 0; ks < 4; ks++) {
            int cur = ks & 1;
            if (ks < 3) {
                int nb = cur ^ 1;
                uint32_t x = (uint32_t)((ks + 1) * 32);
#pragma unroll
                for (int mt = 0; mt < 4; mt++)
                    LDSM4(afr[nb][mt][0], afr[nb][mt][1], afr[nb][mt][2], afr[nb][mt][3],
                          baseA + (aOff[mt] ^ x));
#pragma unroll
                for (int bp = 0; bp < 2; bp++) {
                    uint32_t r0, r1, r2, r3;
                    LDSM4(r0, r1, r2, r3, baseB + (bOff[bp] ^ x));
                    bfr[nb][2 * bp][0] = r0;     bfr[nb][2 * bp][1] = r1;
                    bfr[nb][2 * bp + 1][0] = r2; bfr[nb][2 * bp + 1][1] = r3;
                }
            }
#pragma unroll
            for (int mt = 0; mt < 4; mt++)
#pragma unroll
                for (int nt = 0; nt < 4; nt++)
                    MMA_TF32(acc[mt][nt], afr[cur][mt], bfr[cur][nt][0], bfr[cur][nt][1]);
        }
    }

    int r = lane >> 2, c = (lane & 3) * 2;
#pragma unroll
    for (int mt = 0; mt < 4; mt++) {
        int grow = M0 + wm * 64 + mt * 16 + r;
#pragma unroll
        for (int nt = 0; nt < 4; nt++) {
            int gcol = wn * 32 + nt * 8 + c;
            float2 v01 = make_float2(acc[mt][nt][0], acc[mt][nt][1]);
            float2 v23 = make_float2(acc[mt][nt][2], acc[mt][nt][3]);
            if (gcol < 64) {
                if (grow < M)     *(float2*)(C + (size_t)grow * 64 + gcol) = v01;
                if (grow + 8 < M) *(float2*)(C + (size_t)(grow + 8) * 64 + gcol) = v23;
            } else {
                float bx = bias[gcol - 64], by = bias[gcol - 63];
                v01.x += bx; v01.y += by;
                v23.x += bx; v23.y += by;
                if (grow < M)     *(float2*)(C2 + (size_t)grow * 64 + gcol - 64) = v01;
                if (grow + 8 < M) *(float2*)(C2 + (size_t)(grow + 8) * 64 + gcol - 64) = v23;
            }
        }
    }
}

// ===========================================================================
// GATv2 CSR pass (software-pipelined), h = relu(acc/denom + bias), tf32-rounded
// ===========================================================================
__global__ void gat_csr_kernel(const float* __restrict__ XLR,
                               const int* __restrict__ rowptr, const int* __restrict__ colidx,
                               const float* __restrict__ att, const float* __restrict__ bias,
                               float* __restrict__ h) {
    int warp = (blockIdx.x * blockDim.x + threadIdx.x) >> 5;
    int lane = threadIdx.x & 31;
    if (warp >= NN) return;
    int t = warp;
    int base = lane * 8;

    float4 a0 = *(const float4*)(att + base), a1 = *(const float4*)(att + base + 4);
    const float* xrp = XLR + (size_t)t * 512 + 256 + base;
    float4 r0 = *(const float4*)xrp, r1 = *(const float4*)(xrp + 4);

    float acc0 = 0.f, acc1 = 0.f, acc2 = 0.f, acc3 = 0.f;
    float acc4 = 0.f, acc5 = 0.f, acc6 = 0.f, acc7 = 0.f;
    float denom = 0.f;

    int beg = rowptr[t], end = rowptr[t + 1];
    int deg = end - beg;

    int s0 = (deg > 0) ? colidx[beg] : t;
    const float* xp = XLR + (size_t)s0 * 512 + base;
    float4 l0 = *(const float4*)xp, l1 = *(const float4*)(xp + 4);

    for (int k = 0; k <= deg; k++) {
        float4 c0 = l0, c1 = l1;
        if (k < deg) {
            int sn = (k + 1 < deg) ? colidx[beg + k + 1] : t;
            const float* np = XLR + (size_t)sn * 512 + base;
            l0 = *(const float4*)np;
            l1 = *(const float4*)(np + 4);
        }
#define LRELU(v) ((v) > 0.f ? (v) : 0.2f * (v))
        float sum = LRELU(c0.x + r0.x) * a0.x + LRELU(c0.y + r0.y) * a0.y
                  + LRELU(c0.z + r0.z) * a0.z + LRELU(c0.w + r0.w) * a0.w
                  + LRELU(c1.x + r1.x) * a1.x + LRELU(c1.y + r1.y) * a1.y
                  + LRELU(c1.z + r1.z) * a1.z + LRELU(c1.w + r1.w) * a1.w;
#undef LRELU
        sum += __shfl_xor_sync(0xffffffffu, sum, 1);
        sum += __shfl_xor_sync(0xffffffffu, sum, 2);
        sum += __shfl_xor_sync(0xffffffffu, sum, 4);
        float e = expf(sum);
        acc0 += e * c0.x; acc1 += e * c0.y; acc2 += e * c0.z; acc3 += e * c0.w;
        acc4 += e * c1.x; acc5 += e * c1.y; acc6 += e * c1.z; acc7 += e * c1.w;
        denom += e;
    }

    float rd = __frcp_rn(denom + 1e-16f);
    float4 b0v = *(const float4*)(bias + base), b1v = *(const float4*)(bias + base + 4);
    float4 o0 = make_float4(rna_tf32(fmaxf(acc0 * rd + b0v.x, 0.f)),
                            rna_tf32(fmaxf(acc1 * rd + b0v.y, 0.f)),
                            rna_tf32(fmaxf(acc2 * rd + b0v.z, 0.f)),
                            rna_tf32(fmaxf(acc3 * rd + b0v.w, 0.f)));
    float4 o1 = make_float4(rna_tf32(fmaxf(acc4 * rd + b1v.x, 0.f)),
                            rna_tf32(fmaxf(acc5 * rd + b1v.y, 0.f)),
                            rna_tf32(fmaxf(acc6 * rd + b1v.z, 0.f)),
                            rna_tf32(fmaxf(acc7 * rd + b1v.w, 0.f)));
    float* hp = h + (size_t)t * 256 + base;
    *(float4*)hp = o0;
    *(float4*)(hp + 4) = o1;
}

// ===========================================================================
// CSR gather (64-wide), software-pipelined
// ===========================================================================
__global__ void gather_csr64_kernel(const float* __restrict__ p,
                                    const int* __restrict__ rowptr, const int* __restrict__ colidx,
                                    float* __restrict__ dst, int ldd, int relu) {
    int warp = (blockIdx.x * blockDim.x + threadIdx.x) >> 5;
    int lane = threadIdx.x & 31;
    if (warp >= NN) return;
    int t = warp;
    float* dp = dst + (size_t)t * ldd + lane * 2;
    float2 acc = *(float2*)dp;
    int beg = rowptr[t], end = rowptr[t + 1];
    if (beg < end) {
        int s = colidx[beg];
        float2 v = *(const float2*)(p + (size_t)s * 64 + lane * 2);
        for (int j = beg + 1; j < end; j++) {
            int s2 = colidx[j];
            float2 v2 = *(const float2*)(p + (size_t)s2 * 64 + lane * 2);
            acc.x += v.x; acc.y += v.y;
            v = v2;
        }
        acc.x += v.x; acc.y += v.y;
    }
    if (relu) { acc.x = fmaxf(acc.x, 0.f); acc.y = fmaxf(acc.y, 0.f); }
    *(float2*)dp = acc;
}

// ===========================================================================
// Fused GraphConv-2: per 64-row tile, build h1 = relu(H1 + gather(P1)) in
// smem, then dual K=64 SIMT GEMM: P2 = h1@Wrel2; out = h1@Wroot2 + b2.
// Replaces gather_csr64(P1->h1) + gemm64_dual (saves h1 round-trip).
// smem: h1s[64][65] + B1s/B2s[64][64]  (~49.4 KB dynamic)
// ===========================================================================
#define SMEM_GC2 (64 * 65 * 4 + 2 * 64 * 64 * 4 + 256)

__global__ void __launch_bounds__(256, 1)
gc2_fused_kernel(const float* __restrict__ H1, const float* __restrict__ P1,
                 const int* __restrict__ rowptr, const int* __restrict__ colidx,
                 const float* __restrict__ B1, const float* __restrict__ B2,
                 const float* __restrict__ bias,
                 float* __restrict__ P2, float* __restrict__ outp,
                 int ldc2, int M) {
    extern __shared__ char sm_raw[];
    float* h1s = (float*)sm_raw;                       // [64][65]
    float* B1s = h1s + 64 * 65;                        // [64][64]
    float* B2s = B1s + 64 * 64;                        // [64][64]

    int tid = threadIdx.x;
    int lane = tid & 31, w = tid >> 5;                 // 8 warps
    int m0 = blockIdx.x * 64;

    // --- load B tiles (K=64 full): 1024 float4 per B, 4 per thread each ---
#pragma unroll
    for (int i = 0; i < 4; i++) {
        int lin = tid + i * 256;
        int k = lin >> 4, n4 = (lin & 15) * 4;
        *(float4*)&B1s[k * 64 + n4] = *(const float4*)(B1 + (size_t)k * 64 + n4);
        *(float4*)&B2s[k * 64 + n4] = *(const float4*)(B2 + (size_t)k * 64 + n4);
    }

    // --- build h1 tile: warp w handles rows w*8 .. w*8+7, lane owns 2 ch ---
#pragma unroll
    for (int rr = 0; rr < 8; rr++) {
        int row = w * 8 + rr;
        int t = m0 + row;
        float2 acc = make_float2(0.f, 0.f);
        if (t < M) {
            acc = *(const float2*)(H1 + (size_t)t * 64 + lane * 2);
            int beg = rowptr[t], end = rowptr[t + 1];
            if (beg < end) {
                int s = colidx[beg];
                float2 v = *(const float2*)(P1 + (size_t)s * 64 + lane * 2);
                for (int j = beg + 1; j < end; j++) {
                    int s2 = colidx[j];
                    float2 v2 = *(const float2*)(P1 + (size_t)s2 * 64 + lane * 2);
                    acc.x += v.x; acc.y += v.y;
                    v = v2;
                }
                acc.x += v.x; acc.y += v.y;
            }
            acc.x = fmaxf(acc.x, 0.f);
            acc.y = fmaxf(acc.y, 0.f);
        }
        h1s[row * 65 + lane * 2]     = acc.x;
        h1s[row * 65 + lane * 2 + 1] = acc.y;
    }
    __syncthreads();

    // --- dual GEMM: 4x4 micro-tile, tx cols, ty rows ---
    int tx = tid & 15, ty = tid >> 4;
    float acc1[4][4], acc2[4][4];
#pragma unroll
    for (int i = 0; i < 4; i++)
#pragma unroll
        for (int j = 0; j < 4; j++) { acc1[i][j] = 0.f; acc2[i][j] = 0.f; }

#pragma unroll 8
    for (int k = 0; k < 64; k++) {
        float a[4], b1v[4], b2v[4];
#pragma unroll
        for (int i = 0; i < 4; i++) a[i] = h1s[(ty * 4 + i) * 65 + k];
#pragma unroll
        for (int j = 0; j < 4; j++) {
            b1v[j] = B1s[k * 64 + tx * 4 + j];
            b2v[j] = B2s[k * 64 + tx * 4 + j];
        }
#pragma unroll
        for (int i = 0; i < 4; i++)
#pragma unroll
            for (int j = 0; j < 4; j++) {
                acc1[i][j] += a[i] * b1v[j];
                acc2[i][j] += a[i] * b2v[j];
            }
    }

    float bj[4];
#pragma unroll
    for (int j = 0; j < 4; j++) bj[j] = bias[tx * 4 + j];
#pragma unroll
    for (int i = 0; i < 4; i++) {
        int gm = m0 + ty * 4 + i;
        if (gm < M) {
            *(float4*)(P2 + (size_t)gm * 64 + tx * 4) =
                make_float4(acc1[i][0], acc1[i][1], acc1[i][2], acc1[i][3]);
            *(float4*)(outp + (size_t)gm * ldc2 + tx * 4) =
                make_float4(acc2[i][0] + bj[0], acc2[i][1] + bj[1],
                            acc2[i][2] + bj[2], acc2[i][3] + bj[3]);
        }
    }
}

// ===========================================================================
// Host launch: 4-stream fork-join — GEMM spine split across two streams by
// parity (tail-wave overlap); main chains alternate between s0 and sM2.
// ===========================================================================
extern "C" void kernel_launch(void* const* d_in, const int* in_sizes, int n_in,
                              void* d_out, int out_size) {
    const float* x      = (const float*)d_in[0];
    const int*   ei     = (const int*)  d_in[1];   // [R,2,E]
    const float* Wl     = (const float*)d_in[2];   // [R,768,256]
    const float* Wr     = (const float*)d_in[3];
    const float* att    = (const float*)d_in[4];   // [R,4,64]
    const float* bg     = (const float*)d_in[5];   // [R,256]
    const float* Wrel1  = (const float*)d_in[6];   // [R,256,64]
    const float* Wroot1 = (const float*)d_in[7];
    const float* b1     = (const float*)d_in[8];   // [R,64]
    const float* Wrel2  = (const float*)d_in[9];   // [R,64,64]
    const float* Wroot2 = (const float*)d_in[10];
    const float* b2     = (const float*)d_in[11];  // [R,64]
    float* out = (float*)d_out;                    // [N,R,64]

    float* scratch = nullptr;
    cudaGetSymbolAddress((void**)&scratch, g_scratch);
    float* XLRbuf[2] = { scratch + OFF_XLR0, scratch + OFF_XLR1 };
    float* Hb[2]  = { scratch + OFF_H0,   scratch + OFF_H1P };
    float* H1b[2] = { scratch + OFF_H1_0, scratch + OFF_H1_1 };
    float* P1b[2] = { scratch + OFF_P1_0, scratch + OFF_P1_1 };
    float* P2b[2] = { scratch + OFF_P2_0, scratch + OFF_P2_1 };
    float* XR  = scratch + OFF_XR;
    float* WT  = scratch + OFF_WT;
    float* WB1 = scratch + OFF_WB1;

    int *rowptr = nullptr, *colidx = nullptr, *tmp = nullptr, *blksum = nullptr;
    cudaGetSymbolAddress((void**)&rowptr, g_rowptr);
    cudaGetSymbolAddress((void**)&colidx, g_colidx);
    cudaGetSymbolAddress((void**)&tmp, g_tmp);
    cudaGetSymbolAddress((void**)&blksum, g_blksum);
    int* counts = tmp;
    int* cursor = tmp + RN * NN;

    // One-time host-side resources.
    static cudaStream_t sGA = nullptr, sGB = nullptr, sM2 = nullptr;
    static cudaEvent_t evFork, evPre, evCSR, evEnd, evG[RN], evFree[RN];
    if (!sGA) {
        cudaStreamCreateWithFlags(&sGA, cudaStreamNonBlocking);
        cudaStreamCreateWithFlags(&sGB, cudaStreamNonBlocking);
        cudaStreamCreateWithFlags(&sM2, cudaStreamNonBlocking);
        cudaEventCreateWithFlags(&evFork, cudaEventDisableTiming);
        cudaEventCreateWithFlags(&evPre, cudaEventDisableTiming);
        cudaEventCreateWithFlags(&evCSR, cudaEventDisableTiming);
        cudaEventCreateWithFlags(&evEnd, cudaEventDisableTiming);
        for (int r = 0; r < RN; r++) {
            cudaEventCreateWithFlags(&evG[r], cudaEventDisableTiming);
            cudaEventCreateWithFlags(&evFree[r], cudaEventDisableTiming);
        }
        cudaFuncSetAttribute(gemm_big_kernel,
                             cudaFuncAttributeMaxDynamicSharedMemorySize, SMEM_BIG);
        cudaFuncSetAttribute(gemm_dual_kernel,
                             cudaFuncAttributeMaxDynamicSharedMemorySize, SMEM_GEMM);
        cudaFuncSetAttribute(gc2_fused_kernel,
                             cudaFuncAttributeMaxDynamicSharedMemorySize, SMEM_GC2);
    }

    const int M = NN;
    int nodeBlocks = (NN * 32 + 255) / 256;   // warp per node
    cudaStream_t s0 = 0;  // capture-origin stream

    // --- preprocessing: rounding/transposes on s0; CSR build on sM2 ---
    round_tf32_kernel<<<4096, 256, 0, s0>>>((const float4*)x, (float4*)XR, NN * DD / 4);
    cudaEventRecord(evFork, s0);
    cudaStreamWaitEvent(sM2, evFork, 0);

    // sM2: CSR build with 3-phase parallel scan
    zero_int_kernel<<<1024, 256, 0, sM2>>>(tmp, 2 * RN * NN);
    hist_kernel<<<(RN * EE + 255) / 256, 256, 0, sM2>>>(ei, counts);
    blocksum_kernel<<<dim3(CHUNKS, RN), 256, 0, sM2>>>(counts, blksum);
    blkscan_kernel<<<RN, 32, 0, sM2>>>(blksum);
    chunkscan_kernel<<<dim3(CHUNKS, RN), 1024, 0, sM2>>>(counts, blksum, rowptr);
    fillcsr_kernel<<<(RN * EE + 255) / 256, 256, 0, sM2>>>(ei, rowptr, cursor, colidx);
    cudaEventRecord(evCSR, sM2);

    // s0: weight transposes
    transpose_w_kernel<<<dim3(24, 16, RN), dim3(32, 8), 0, s0>>>(Wl, Wr, WT);
    transpose_wb1_kernel<<<dim3(8, 4, RN), dim3(32, 8), 0, s0>>>(Wrel1, Wroot1, WB1);
    cudaEventRecord(evPre, s0);

    cudaStreamWaitEvent(sGA, evPre, 0);  // GEMMs need XR + WT
    cudaStreamWaitEvent(sGB, evPre, 0);
    cudaStreamWaitEvent(s0, evCSR, 0);   // parity-0 mains need CSR
    cudaStreamWaitEvent(sM2, evPre, 0);  // parity-1 mains need WB1

    for (int r = 0; r < RN; r++) {
        const int* rp = rowptr + r * (NN + 1);
        const int* ci = colidx + r * EE;
        int par = r & 1;
        float* XLR = XLRbuf[par];
        cudaStream_t sP = par ? sM2 : s0;
        cudaStream_t sG = par ? sGB : sGA;   // GEMM stream by parity

        // --- GEMM for relation r (BN=256, 512 threads) on its parity stream ---
        if (r >= 2) cudaStreamWaitEvent(sG, evFree[r - 2], 0);
        gemm_big_kernel<<<dim3(2, (M + GBM - 1) / GBM), 512, SMEM_BIG, sG>>>(
            XR, WT + (size_t)r * 512 * DD, XLR, M);
        cudaEventRecord(evG[r], sG);

        // --- main chain for relation r on its parity stream ---
        cudaStreamWaitEvent(sP, evG[r], 0);

        gat_csr_kernel<<<nodeBlocks, 256, 0, sP>>>(XLR, rp, ci,
                                                   att + (size_t)r * HC,
                                                   bg + (size_t)r * HC, Hb[par]);
        cudaEventRecord(evFree[r], sP);  // last reader of XLRbuf[par]

        // GraphConv 1 (tensor): P1 = h@Wrel1, H1 = h@Wroot1 + b1
        gemm_dual_kernel<<<dim3(1, (M + BM - 1) / BM), 256, SMEM_GEMM, sP>>>(
            Hb[par], WB1 + (size_t)r * 128 * HC, P1b[par], H1b[par],
            b1 + (size_t)r * OO, M);

        // GraphConv 2 fused: h1 tile (gather+relu) + dual GEMM -> P2, out-partial
        gc2_fused_kernel<<<(M + 63) / 64, 256, SMEM_GC2, sP>>>(
            H1b[par], P1b[par], rp, ci,
            Wrel2 + (size_t)r * OO * OO, Wroot2 + (size_t)r * OO * OO,
            b2 + (size_t)r * OO, P2b[par], out + (size_t)r * OO, RN * OO, M);

        // final gather: out[t] += sum P2[s]
        gather_csr64_kernel<<<nodeBlocks, 256, 0, sP>>>(P2b[par], rp, ci,
                                                        out + (size_t)r * OO, RN * OO, 0);
    }

    // join parity-1 stream back into the capture-origin stream
    cudaEventRecord(evEnd, sM2);
    cudaStreamWaitEvent(s0, evEnd, 0);
}

// round 14
// speedup vs baseline: 1.0073x; 1.0073x over previous
#include <cuda_runtime.h>
#include <cstdint>
#include <cstddef>

// Problem constants (fixed by the reference)
#define RN 6
#define NN 50000
#define EE 200000
#define DD 768
#define HC 256      // H*C
#define OO 64

// ---------------------------------------------------------------------------
// Scratch layout (floats) — XLR now per-relation (6 buffers, no reuse hazard)
// ---------------------------------------------------------------------------
__device__ float g_scratch[239355904];

#define XLR_STRIDE 25600000u
#define OFF_XLR0  0u                   // 6 x 25,600,000
#define OFF_H0    153600000u
#define OFF_H1P   166400000u
#define OFF_H1_0  179200000u
#define OFF_H1_1  182400000u
#define OFF_P1_0  185600000u
#define OFF_P1_1  188800000u
#define OFF_P2_0  192000000u
#define OFF_P2_1  195200000u
#define OFF_XR    198400000u
#define OFF_WT    236800000u
#define OFF_WB1   239159296u

// CSR structures (ints)
#define CHUNKS 49   // ceil(NN / 1024)
__device__ int g_rowptr[RN * (NN + 1)];
__device__ int g_colidx[RN * EE];
__device__ int g_tmp[2 * RN * NN];        // counts | cursor
__device__ int g_blksum[RN * CHUNKS];

// ===========================================================================
// PTX helpers (plain-sm_103-legal: cp.async, ldmatrix, mma.sync)
// ===========================================================================
__device__ __forceinline__ uint32_t smem_u32(const void* p) {
    uint32_t a;
    asm("{ .reg .u64 t; cvta.to.shared.u64 t, %1; cvt.u32.u64 %0, t; }"
        : "=r"(a) : "l"(p));
    return a;
}
__device__ __forceinline__ void cp16(uint32_t dst, const void* src, uint32_t sz) {
    asm volatile("cp.async.cg.shared.global [%0], [%1], 16, %2;"
                 :: "r"(dst), "l"(src), "r"(sz) : "memory");
}
__device__ __forceinline__ void cp_commit() {
    asm volatile("cp.async.commit_group;" ::: "memory");
}
__device__ __forceinline__ void cp_wait1() {
    asm volatile("cp.async.wait_group 1;" ::: "memory");
}
__device__ __forceinline__ void cp_wait2() {
    asm volatile("cp.async.wait_group 2;" ::: "memory");
}
#define LDSM4(r0, r1, r2, r3, addr) \
    asm volatile("ldmatrix.sync.aligned.m8n8.x4.shared.b16 {%0,%1,%2,%3}, [%4];" \
                 : "=r"(r0), "=r"(r1), "=r"(r2), "=r"(r3) : "r"(addr))

#define MMA_TF32(d, a, b0, b1) \
    asm volatile("mma.sync.aligned.m16n8k8.row.col.f32.tf32.tf32.f32 " \
                 "{%0,%1,%2,%3}, {%4,%5,%6,%7}, {%8,%9}, {%0,%1,%2,%3};" \
                 : "+f"((d)[0]), "+f"((d)[1]), "+f"((d)[2]), "+f"((d)[3]) \
                 : "r"((a)[0]), "r"((a)[1]), "r"((a)[2]), "r"((a)[3]), \
                   "r"(b0), "r"(b1))

// ===========================================================================
// Preprocessing: tf32 rounding + weight transposes
// ===========================================================================
__device__ __forceinline__ float rna_tf32(float v) {
    uint32_t o;
    asm("cvt.rna.tf32.f32 %0, %1;" : "=r"(o) : "f"(v));
    return __uint_as_float(o);
}

__global__ void round_tf32_kernel(const float4* __restrict__ in, float4* __restrict__ out, int n4) {
    int i = blockIdx.x * blockDim.x + threadIdx.x;
    int stride = gridDim.x * blockDim.x;
    for (; i < n4; i += stride) {
        float4 v = in[i];
        v.x = rna_tf32(v.x); v.y = rna_tf32(v.y);
        v.z = rna_tf32(v.z); v.w = rna_tf32(v.w);
        out[i] = v;
    }
}

// WT[r][n][k] = rna(Wl[r][k][n]) for n<256 else rna(Wr[r][k][n-256])
__global__ void transpose_w_kernel(const float* __restrict__ Wl, const float* __restrict__ Wr,
                                   float* __restrict__ WT) {
    __shared__ float tile[32][33];
    int r = blockIdx.z;
    int k0 = blockIdx.x * 32;
    int n0 = blockIdx.y * 32;
    const float* W = (n0 < 256) ? Wl : Wr;
    int nc0 = (n0 < 256) ? n0 : (n0 - 256);
    int tx = threadIdx.x, ty = threadIdx.y;  // 32 x 8
#pragma unroll
    for (int i = 0; i < 32; i += 8) {
        float v = W[((size_t)r * DD + k0 + ty + i) * HC + nc0 + tx];
        tile[ty + i][tx] = rna_tf32(v);
    }
    __syncthreads();
#pragma unroll
    for (int i = 0; i < 32; i += 8) {
        WT[((size_t)r * 512 + n0 + ty + i) * DD + k0 + tx] = tile[tx][ty + i];
    }
}

// WB1[r][n][k] = rna(Wrel1[r][k][n]) for n<64 else rna(Wroot1[r][k][n-64]); K=256
__global__ void transpose_wb1_kernel(const float* __restrict__ Wrel1,
                                     const float* __restrict__ Wroot1,
                                     float* __restrict__ WB1) {
    __shared__ float tile[32][33];
    int r = blockIdx.z;
    int k0 = blockIdx.x * 32;
    int n0 = blockIdx.y * 32;
    const float* W = (n0 < 64) ? Wrel1 : Wroot1;
    int nc0 = (n0 < 64) ? n0 : (n0 - 64);
    int tx = threadIdx.x, ty = threadIdx.y;  // 32 x 8
#pragma unroll
    for (int i = 0; i < 32; i += 8) {
        float v = W[((size_t)r * HC + k0 + ty + i) * OO + nc0 + tx];
        tile[ty + i][tx] = rna_tf32(v);
    }
    __syncthreads();
#pragma unroll
    for (int i = 0; i < 32; i += 8) {
        WB1[((size_t)r * 128 + n0 + ty + i) * HC + k0 + tx] = tile[tx][ty + i];
    }
}

// ===========================================================================
// CSR build: zero -> histogram -> 3-phase parallel scan -> fill
// ===========================================================================
__global__ void zero_int_kernel(int* p, int n) {
    int i = blockIdx.x * blockDim.x + threadIdx.x;
    int stride = gridDim.x * blockDim.x;
    for (; i < n; i += stride) p[i] = 0;
}

__global__ void hist_kernel(const int* __restrict__ ei, int* __restrict__ counts) {
    int i = blockIdx.x * blockDim.x + threadIdx.x;
    if (i >= RN * EE) return;
    int r = i / EE, e = i - r * EE;
    int t = ei[(size_t)r * 2 * EE + EE + e];
    atomicAdd(&counts[r * NN + t], 1);
}

__global__ void blocksum_kernel(const int* __restrict__ counts, int* __restrict__ blksum) {
    __shared__ int sred[256];
    int r = blockIdx.y;
    int c0 = blockIdx.x * 1024;
    const int* c = counts + r * NN;
    int s = 0;
#pragma unroll
    for (int k = 0; k < 4; k++) {
        int i = c0 + threadIdx.x + k * 256;
        if (i < NN) s += c[i];
    }
    sred[threadIdx.x] = s;
    __syncthreads();
    for (int off = 128; off > 0; off >>= 1) {
        if (threadIdx.x < off) sred[threadIdx.x] += sred[threadIdx.x + off];
        __syncthreads();
    }
    if (threadIdx.x == 0) blksum[r * CHUNKS + blockIdx.x] = sred[0];
}

__global__ void blkscan_kernel(int* __restrict__ blksum) {
    int r = blockIdx.x;
    if (threadIdx.x == 0) {
        int acc = 0;
        for (int i = 0; i < CHUNKS; i++) {
            int v = blksum[r * CHUNKS + i];
            blksum[r * CHUNKS + i] = acc;
            acc += v;
        }
    }
}

__global__ void __launch_bounds__(1024)
chunkscan_kernel(const int* __restrict__ counts, const int* __restrict__ blksum,
                 int* __restrict__ rowptr) {
    __shared__ int sdata[1024];
    int r = blockIdx.y;
    int i = blockIdx.x * 1024 + threadIdx.x;
    const int* c = counts + r * NN;
    int v = (i < NN) ? c[i] : 0;
    sdata[threadIdx.x] = v;
    __syncthreads();
#pragma unroll
    for (int off = 1; off < 1024; off <<= 1) {
        int tv = (threadIdx.x >= off) ? sdata[threadIdx.x - off] : 0;
        __syncthreads();
        sdata[threadIdx.x] += tv;
        __syncthreads();
    }
    int* rp = rowptr + r * (NN + 1);
    int offc = blksum[r * CHUNKS + blockIdx.x];
    if (i < NN) rp[i + 1] = offc + sdata[threadIdx.x];
    if (i == 0) rp[0] = 0;
}

__global__ void fillcsr_kernel(const int* __restrict__ ei, const int* __restrict__ rowptr,
                               int* __restrict__ cursor, int* __restrict__ colidx) {
    int i = blockIdx.x * blockDim.x + threadIdx.x;
    if (i >= RN * EE) return;
    int r = i / EE, e = i - r * EE;
    int s = ei[(size_t)r * 2 * EE + e];
    int t = ei[(size_t)r * 2 * EE + EE + e];
    int pos = rowptr[r * (NN + 1) + t] + atomicAdd(&cursor[r * NN + t], 1);
    colidx[r * EE + pos] = s;
}

// ===========================================================================
// Big tf32 GEMM: BM=128 BN=256 BK=32, 512 threads (16 warps, 2m x 8n),
// warp tile 64x32, 3-stage cp.async. C[M][512] tile = A @ B^T. (proven R11)
// ===========================================================================
#define GBM 128
#define GBN 256
#define GBK 32
#define GST 3
#define A_TB (GBM * GBK * 4)      // 16384
#define B_TB (GBN * GBK * 4)      // 32768
#define KIT24 24
#define SMEM_BIG (GST * (A_TB + B_TB) + 1024)   // 148480

__global__ void __launch_bounds__(512, 1)
gemm_big_kernel(const float* __restrict__ A, const float* __restrict__ B,
                float* __restrict__ C, int M) {
    extern __shared__ char sm_raw[];
    uint32_t smbase = (smem_u32(sm_raw) + 1023u) & ~1023u;
    uint32_t sA = smbase;                    // 3 x 16KB
    uint32_t sB = smbase + GST * A_TB;       // 3 x 32KB

    const int K = DD;
    int tid = threadIdx.x;
    int lane = tid & 31, wid = tid >> 5;     // 16 warps
    int wm = wid & 1, wn = wid >> 1;         // 2 x 8
    int M0 = blockIdx.y * GBM, N0 = blockIdx.x * GBN;

    uint32_t dstA[2]; const float* srcA[2]; uint32_t szA[2];
#pragma unroll
    for (int i = 0; i < 2; i++) {
        int lin = tid + i * 512;
        int row = lin >> 3, ch = lin & 7;
        dstA[i] = row * 128 + ((ch * 16) ^ ((row & 7) * 16));
        int ga = M0 + row;
        szA[i] = (ga < M) ? 16u : 0u;
        srcA[i] = A + (size_t)(ga < M ? ga : 0) * K + ch * 4;
    }
    uint32_t dstB[4]; const float* srcB[4];
#pragma unroll
    for (int i = 0; i < 4; i++) {
        int lin = tid + i * 512;
        int row = lin >> 3, ch = lin & 7;    // row 0..255
        dstB[i] = row * 128 + ((ch * 16) ^ ((row & 7) * 16));
        srcB[i] = B + (size_t)(N0 + row) * K + ch * 4;
    }

    uint32_t aOff[4], bOff[2];
#pragma unroll
    for (int mt = 0; mt < 4; mt++) {
        int rowA = wm * 64 + mt * 16 + (lane & 7) + ((lane >> 3) & 1) * 8;
        uint32_t q = (uint32_t)(((lane >> 4) * 16) ^ ((rowA & 7) * 16));
        aOff[mt] = (uint32_t)rowA * 128 + q;
    }
#pragma unroll
    for (int bp = 0; bp < 2; bp++) {
        int rowB = wn * 32 + bp * 16 + (lane & 7) + ((lane >> 4) & 1) * 8;
        uint32_t q = (uint32_t)((((lane >> 3) & 1) * 16) ^ ((rowB & 7) * 16));
        bOff[bp] = (uint32_t)rowB * 128 + q;
    }

    float acc[4][4][4];
#pragma unroll
    for (int mt = 0; mt < 4; mt++)
#pragma unroll
        for (int nt = 0; nt < 4; nt++)
#pragma unroll
            for (int j = 0; j < 4; j++) acc[mt][nt][j] = 0.f;

#define FILL_STAGE(st, k0)                                          \
    do {                                                            \
        _Pragma("unroll")                                           \
        for (int i = 0; i < 2; i++)                                 \
            cp16(sA + (st) * A_TB + dstA[i], srcA[i] + (k0), szA[i]); \
        _Pragma("unroll")                                           \
        for (int i = 0; i < 4; i++)                                 \
            cp16(sB + (st) * B_TB + dstB[i], srcB[i] + (k0), 16u);  \
    } while (0)

    FILL_STAGE(0, 0);
    cp_commit();
    FILL_STAGE(1, GBK);
    cp_commit();

    for (int it = 0; it < KIT24; it++) {
        cp_wait1();
        __syncthreads();

        int nx = it + 2;
        if (nx < KIT24) {
            int s2 = nx % GST;
            FILL_STAGE(s2, nx * GBK);
        }
        cp_commit();

        int s = it % GST;
        uint32_t baseA = sA + s * A_TB;
        uint32_t baseB = sB + s * B_TB;

#pragma unroll
        for (int ks = 0; ks < 4; ks++) {
            uint32_t x = (uint32_t)(ks * 32);
            uint32_t afr[4][4];
            uint32_t bfr[4][2];
#pragma unroll
            for (int mt = 0; mt < 4; mt++)
                LDSM4(afr[mt][0], afr[mt][1], afr[mt][2], afr[mt][3],
                      baseA + (aOff[mt] ^ x));
#pragma unroll
            for (int bp = 0; bp < 2; bp++) {
                uint32_t r0, r1, r2, r3;
                LDSM4(r0, r1, r2, r3, baseB + (bOff[bp] ^ x));
                bfr[2 * bp][0] = r0;     bfr[2 * bp][1] = r1;
                bfr[2 * bp + 1][0] = r2; bfr[2 * bp + 1][1] = r3;
            }
#pragma unroll
            for (int mt = 0; mt < 4; mt++)
#pragma unroll
                for (int nt = 0; nt < 4; nt++)
                    MMA_TF32(acc[mt][nt], afr[mt], bfr[nt][0], bfr[nt][1]);
        }
    }
#undef FILL_STAGE

    int r = lane >> 2, c = (lane & 3) * 2;
#pragma unroll
    for (int mt = 0; mt < 4; mt++) {
        int grow = M0 + wm * 64 + mt * 16 + r;
#pragma unroll
        for (int nt = 0; nt < 4; nt++) {
            int gcol = N0 + wn * 32 + nt * 8 + c;
            if (grow < M)
                *(float2*)(C + (size_t)grow * 512 + gcol) =
                    make_float2(acc[mt][nt][0], acc[mt][nt][1]);
            if (grow + 8 < M)
                *(float2*)(C + (size_t)(grow + 8) * 512 + gcol) =
                    make_float2(acc[mt][nt][2], acc[mt][nt][3]);
        }
    }
}

// ===========================================================================
// DUAL tf32 GEMM (GraphConv-1) — proven version. BM=128 BN=128 BK=32,
// 4-stage, 256 threads, KITN=8, ks-double-buffered fragments.
// ===========================================================================
#define BM 128
#define BN 128
#define BK 32
#define GSTG 4
#define TILE_BYTES (BM * BK * 4)
#define SMEM_GEMM (GSTG * 2 * TILE_BYTES + 1024)

__global__ void __launch_bounds__(256, 1)
gemm_dual_kernel(const float* __restrict__ A, const float* __restrict__ B,
                 float* __restrict__ C, float* __restrict__ C2,
                 const float* __restrict__ bias, int M) {
    extern __shared__ char sm_raw[];
    uint32_t smbase = (smem_u32(sm_raw) + 1023u) & ~1023u;
    uint32_t sA = smbase;
    uint32_t sB = smbase + GSTG * TILE_BYTES;
    const int K = HC;
    const int KITN = 8;

    int tid = threadIdx.x;
    int lane = tid & 31, wid = tid >> 5;
    int wm = wid & 1, wn = wid >> 1;
    int M0 = blockIdx.y * BM;

    uint32_t dstOff[4];
    const float* srcA[4]; uint32_t szA[4];
    const float* srcB[4];
#pragma unroll
    for (int i = 0; i < 4; i++) {
        int lin = tid + i * 256;
        int row = lin >> 3, ch = lin & 7;
        dstOff[i] = row * 128 + ((ch * 16) ^ ((row & 7) * 16));
        int ga = M0 + row;
        szA[i] = (ga < M) ? 16u : 0u;
        srcA[i] = A + (size_t)(ga < M ? ga : 0) * K + ch * 4;
        srcB[i] = B + (size_t)row * K + ch * 4;
    }

    uint32_t aOff[4], bOff[2];
#pragma unroll
    for (int mt = 0; mt < 4; mt++) {
        int rowA = wm * 64 + mt * 16 + (lane & 7) + ((lane >> 3) & 1) * 8;
        uint32_t q = (uint32_t)(((lane >> 4) * 16) ^ ((rowA & 7) * 16));
        aOff[mt] = (uint32_t)rowA * 128 + q;
    }
#pragma unroll
    for (int bp = 0; bp < 2; bp++) {
        int rowB = wn * 32 + bp * 16 + (lane & 7) + ((lane >> 4) & 1) * 8;
        uint32_t q = (uint32_t)((((lane >> 3) & 1) * 16) ^ ((rowB & 7) * 16));
        bOff[bp] = (uint32_t)rowB * 128 + q;
    }

    float acc[4][4][4];
#pragma unroll
    for (int mt = 0; mt < 4; mt++)
#pragma unroll
        for (int nt = 0; nt < 4; nt++)
#pragma unroll
            for (int j = 0; j < 4; j++) acc[mt][nt][j] = 0.f;

#pragma unroll
    for (int s = 0; s < 3; s++) {
#pragma unroll
        for (int i = 0; i < 4; i++) {
            cp16(sA + s * TILE_BYTES + dstOff[i], srcA[i] + s * BK, szA[i]);
            cp16(sB + s * TILE_BYTES + dstOff[i], srcB[i] + s * BK, 16u);
        }
        cp_commit();
    }

    uint32_t afr[2][4][4];
    uint32_t bfr[2][4][2];

    for (int it = 0; it < KITN; it++) {
        cp_wait2();
        __syncthreads();

        int nx = it + 3;
        if (nx < KITN) {
            int s2 = nx % GSTG;
#pragma unroll
            for (int i = 0; i < 4; i++) {
                cp16(sA + s2 * TILE_BYTES + dstOff[i], srcA[i] + nx * BK, szA[i]);
                cp16(sB + s2 * TILE_BYTES + dstOff[i], srcB[i] + nx * BK, 16u);
            }
        }
        cp_commit();

        int s = it % GSTG;
        uint32_t baseA = sA + s * TILE_BYTES;
        uint32_t baseB = sB + s * TILE_BYTES;

#pragma unroll
        for (int mt = 0; mt < 4; mt++)
            LDSM4(afr[0][mt][0], afr[0][mt][1], afr[0][mt][2], afr[0][mt][3],
                  baseA + aOff[mt]);
#pragma unroll
        for (int bp = 0; bp < 2; bp++) {
            uint32_t r0, r1, r2, r3;
            LDSM4(r0, r1, r2, r3, baseB + bOff[bp]);
            bfr[0][2 * bp][0] = r0;     bfr[0][2 * bp][1] = r1;
            bfr[0][2 * bp + 1][0] = r2; bfr[0][2 * bp + 1][1] = r3;
        }

#pragma unroll
        for (int ks = 0; ks < 4; ks++) {
            int cur = ks & 1;
            if (ks < 3) {
                int nb = cur ^ 1;
                uint32_t x = (uint32_t)((ks + 1) * 32);
#pragma unroll
                for (int mt = 0; mt < 4; mt++)
                    LDSM4(afr[nb][mt][0], afr[nb][mt][1], afr[nb][mt][2], afr[nb][mt][3],
                          baseA + (aOff[mt] ^ x));
#pragma unroll
                for (int bp = 0; bp < 2; bp++) {
                    uint32_t r0, r1, r2, r3;
                    LDSM4(r0, r1, r2, r3, baseB + (bOff[bp] ^ x));
                    bfr[nb][2 * bp][0] = r0;     bfr[nb][2 * bp][1] = r1;
                    bfr[nb][2 * bp + 1][0] = r2; bfr[nb][2 * bp + 1][1] = r3;
                }
            }
#pragma unroll
            for (int mt = 0; mt < 4; mt++)
#pragma unroll
                for (int nt = 0; nt < 4; nt++)
                    MMA_TF32(acc[mt][nt], afr[cur][mt], bfr[cur][nt][0], bfr[cur][nt][1]);
        }
    }

    int r = lane >> 2, c = (lane & 3) * 2;
#pragma unroll
    for (int mt = 0; mt < 4; mt++) {
        int grow = M0 + wm * 64 + mt * 16 + r;
#pragma unroll
        for (int nt = 0; nt < 4; nt++) {
            int gcol = wn * 32 + nt * 8 + c;
            float2 v01 = make_float2(acc[mt][nt][0], acc[mt][nt][1]);
            float2 v23 = make_float2(acc[mt][nt][2], acc[mt][nt][3]);
            if (gcol < 64) {
                if (grow < M)     *(float2*)(C + (size_t)grow * 64 + gcol) = v01;
                if (grow + 8 < M) *(float2*)(C + (size_t)(grow + 8) * 64 + gcol) = v23;
            } else {
                float bx = bias[gcol - 64], by = bias[gcol - 63];
                v01.x += bx; v01.y += by;
                v23.x += bx; v23.y += by;
                if (grow < M)     *(float2*)(C2 + (size_t)grow * 64 + gcol - 64) = v01;
                if (grow + 8 < M) *(float2*)(C2 + (size_t)(grow + 8) * 64 + gcol - 64) = v23;
            }
        }
    }
}

// ===========================================================================
// GATv2 CSR pass (software-pipelined), h = relu(acc/denom + bias), tf32-rounded
// ===========================================================================
__global__ void gat_csr_kernel(const float* __restrict__ XLR,
                               const int* __restrict__ rowptr, const int* __restrict__ colidx,
                               const float* __restrict__ att, const float* __restrict__ bias,
                               float* __restrict__ h) {
    int warp = (blockIdx.x * blockDim.x + threadIdx.x) >> 5;
    int lane = threadIdx.x & 31;
    if (warp >= NN) return;
    int t = warp;
    int base = lane * 8;

    float4 a0 = *(const float4*)(att + base), a1 = *(const float4*)(att + base + 4);
    const float* xrp = XLR + (size_t)t * 512 + 256 + base;
    float4 r0 = *(const float4*)xrp, r1 = *(const float4*)(xrp + 4);

    float acc0 = 0.f, acc1 = 0.f, acc2 = 0.f, acc3 = 0.f;
    float acc4 = 0.f, acc5 = 0.f, acc6 = 0.f, acc7 = 0.f;
    float denom = 0.f;

    int beg = rowptr[t], end = rowptr[t + 1];
    int deg = end - beg;

    int s0 = (deg > 0) ? colidx[beg] : t;
    const float* xp = XLR + (size_t)s0 * 512 + base;
    float4 l0 = *(const float4*)xp, l1 = *(const float4*)(xp + 4);

    for (int k = 0; k <= deg; k++) {
        float4 c0 = l0, c1 = l1;
        if (k < deg) {
            int sn = (k + 1 < deg) ? colidx[beg + k + 1] : t;
            const float* np = XLR + (size_t)sn * 512 + base;
            l0 = *(const float4*)np;
            l1 = *(const float4*)(np + 4);
        }
#define LRELU(v) ((v) > 0.f ? (v) : 0.2f * (v))
        float sum = LRELU(c0.x + r0.x) * a0.x + LRELU(c0.y + r0.y) * a0.y
                  + LRELU(c0.z + r0.z) * a0.z + LRELU(c0.w + r0.w) * a0.w
                  + LRELU(c1.x + r1.x) * a1.x + LRELU(c1.y + r1.y) * a1.y
                  + LRELU(c1.z + r1.z) * a1.z + LRELU(c1.w + r1.w) * a1.w;
#undef LRELU
        sum += __shfl_xor_sync(0xffffffffu, sum, 1);
        sum += __shfl_xor_sync(0xffffffffu, sum, 2);
        sum += __shfl_xor_sync(0xffffffffu, sum, 4);
        float e = expf(sum);
        acc0 += e * c0.x; acc1 += e * c0.y; acc2 += e * c0.z; acc3 += e * c0.w;
        acc4 += e * c1.x; acc5 += e * c1.y; acc6 += e * c1.z; acc7 += e * c1.w;
        denom += e;
    }

    float rd = __frcp_rn(denom + 1e-16f);
    float4 b0v = *(const float4*)(bias + base), b1v = *(const float4*)(bias + base + 4);
    float4 o0 = make_float4(rna_tf32(fmaxf(acc0 * rd + b0v.x, 0.f)),
                            rna_tf32(fmaxf(acc1 * rd + b0v.y, 0.f)),
                            rna_tf32(fmaxf(acc2 * rd + b0v.z, 0.f)),
                            rna_tf32(fmaxf(acc3 * rd + b0v.w, 0.f)));
    float4 o1 = make_float4(rna_tf32(fmaxf(acc4 * rd + b1v.x, 0.f)),
                            rna_tf32(fmaxf(acc5 * rd + b1v.y, 0.f)),
                            rna_tf32(fmaxf(acc6 * rd + b1v.z, 0.f)),
                            rna_tf32(fmaxf(acc7 * rd + b1v.w, 0.f)));
    float* hp = h + (size_t)t * 256 + base;
    *(float4*)hp = o0;
    *(float4*)(hp + 4) = o1;
}

// ===========================================================================
// CSR gather (64-wide), software-pipelined
// ===========================================================================
__global__ void gather_csr64_kernel(const float* __restrict__ p,
                                    const int* __restrict__ rowptr, const int* __restrict__ colidx,
                                    float* __restrict__ dst, int ldd, int relu) {
    int warp = (blockIdx.x * blockDim.x + threadIdx.x) >> 5;
    int lane = threadIdx.x & 31;
    if (warp >= NN) return;
    int t = warp;
    float* dp = dst + (size_t)t * ldd + lane * 2;
    float2 acc = *(float2*)dp;
    int beg = rowptr[t], end = rowptr[t + 1];
    if (beg < end) {
        int s = colidx[beg];
        float2 v = *(const float2*)(p + (size_t)s * 64 + lane * 2);
        for (int j = beg + 1; j < end; j++) {
            int s2 = colidx[j];
            float2 v2 = *(const float2*)(p + (size_t)s2 * 64 + lane * 2);
            acc.x += v.x; acc.y += v.y;
            v = v2;
        }
        acc.x += v.x; acc.y += v.y;
    }
    if (relu) { acc.x = fmaxf(acc.x, 0.f); acc.y = fmaxf(acc.y, 0.f); }
    *(float2*)dp = acc;
}

// ===========================================================================
// Dual small GEMM (SIMT, K=64 layer)
// ===========================================================================
__global__ void __launch_bounds__(256)
gemm64_dual_kernel(const float* __restrict__ A,
                   const float* __restrict__ B1, const float* __restrict__ B2,
                   const float* __restrict__ bias,
                   float* __restrict__ C1, float* __restrict__ C2,
                   int ldc2, int M, int K) {
    __shared__ float As[32][68];
    __shared__ float B1s[32][64];
    __shared__ float B2s[32][64];
    int m0 = blockIdx.x * 64;
    int tid = threadIdx.x;
    int tx = tid & 15, ty = tid >> 4;
    float acc1[4][4], acc2[4][4];
#pragma unroll
    for (int i = 0; i < 4; i++)
#pragma unroll
        for (int j = 0; j < 4; j++) { acc1[i][j] = 0.f; acc2[i][j] = 0.f; }

    for (int k0 = 0; k0 < K; k0 += 32) {
#pragma unroll
        for (int l = 0; l < 2; l++) {
            int lin = tid + l * 256;
            int row = lin >> 3, kc = (lin & 7) * 4;
            float4 v = make_float4(0.f, 0.f, 0.f, 0.f);
            int gm = m0 + row;
            if (gm < M) v = *(const float4*)(A + (size_t)gm * K + k0 + kc);
            As[kc + 0][row] = v.x; As[kc + 1][row] = v.y;
            As[kc + 2][row] = v.z; As[kc + 3][row] = v.w;

            int br = lin >> 4, bc = (lin & 15) * 4;
            *(float4*)&B1s[br][bc] = *(const float4*)(B1 + (size_t)(k0 + br) * 64 + bc);
            *(float4*)&B2s[br][bc] = *(const float4*)(B2 + (size_t)(k0 + br) * 64 + bc);
        }
        __syncthreads();
#pragma unroll
        for (int k = 0; k < 32; k++) {
            float a[4], b1v[4], b2v[4];
#pragma unroll
            for (int i = 0; i < 4; i++) a[i] = As[k][ty * 4 + i];
#pragma unroll
            for (int j = 0; j < 4; j++) { b1v[j] = B1s[k][tx * 4 + j]; b2v[j] = B2s[k][tx * 4 + j]; }
#pragma unroll
            for (int i = 0; i < 4; i++)
#pragma unroll
                for (int j = 0; j < 4; j++) {
                    acc1[i][j] += a[i] * b1v[j];
                    acc2[i][j] += a[i] * b2v[j];
                }
        }
        __syncthreads();
    }

    float bj[4];
#pragma unroll
    for (int j = 0; j < 4; j++) bj[j] = bias[tx * 4 + j];
#pragma unroll
    for (int i = 0; i < 4; i++) {
        int gm = m0 + ty * 4 + i;
        if (gm < M) {
            *(float4*)(C1 + (size_t)gm * 64 + tx * 4) =
                make_float4(acc1[i][0], acc1[i][1], acc1[i][2], acc1[i][3]);
            *(float4*)(C2 + (size_t)gm * ldc2 + tx * 4) =
                make_float4(acc2[i][0] + bj[0], acc2[i][1] + bj[1],
                            acc2[i][2] + bj[2], acc2[i][3] + bj[3]);
        }
    }
}

// ===========================================================================
// Host launch: 4-stream fork-join. GEMMs are fully independent now (one XLR
// buffer per relation) and alternate across two GEMM streams; main chains
// alternate between s0 and sM2.
// ===========================================================================
extern "C" void kernel_launch(void* const* d_in, const int* in_sizes, int n_in,
                              void* d_out, int out_size) {
    const float* x      = (const float*)d_in[0];
    const int*   ei     = (const int*)  d_in[1];   // [R,2,E]
    const float* Wl     = (const float*)d_in[2];   // [R,768,256]
    const float* Wr     = (const float*)d_in[3];
    const float* att    = (const float*)d_in[4];   // [R,4,64]
    const float* bg     = (const float*)d_in[5];   // [R,256]
    const float* Wrel1  = (const float*)d_in[6];   // [R,256,64]
    const float* Wroot1 = (const float*)d_in[7];
    const float* b1     = (const float*)d_in[8];   // [R,64]
    const float* Wrel2  = (const float*)d_in[9];   // [R,64,64]
    const float* Wroot2 = (const float*)d_in[10];
    const float* b2     = (const float*)d_in[11];  // [R,64]
    float* out = (float*)d_out;                    // [N,R,64]

    float* scratch = nullptr;
    cudaGetSymbolAddress((void**)&scratch, g_scratch);
    float* Hb[2]  = { scratch + OFF_H0,   scratch + OFF_H1P };
    float* H1b[2] = { scratch + OFF_H1_0, scratch + OFF_H1_1 };
    float* P1b[2] = { scratch + OFF_P1_0, scratch + OFF_P1_1 };
    float* P2b[2] = { scratch + OFF_P2_0, scratch + OFF_P2_1 };
    float* XR  = scratch + OFF_XR;
    float* WT  = scratch + OFF_WT;
    float* WB1 = scratch + OFF_WB1;

    int *rowptr = nullptr, *colidx = nullptr, *tmp = nullptr, *blksum = nullptr;
    cudaGetSymbolAddress((void**)&rowptr, g_rowptr);
    cudaGetSymbolAddress((void**)&colidx, g_colidx);
    cudaGetSymbolAddress((void**)&tmp, g_tmp);
    cudaGetSymbolAddress((void**)&blksum, g_blksum);
    int* counts = tmp;
    int* cursor = tmp + RN * NN;

    // One-time host-side resources.
    static cudaStream_t sGA = nullptr, sGB = nullptr, sM2 = nullptr;
    static cudaEvent_t evFork, evPre, evCSR, evEnd, evG[RN];
    if (!sGA) {
        cudaStreamCreateWithFlags(&sGA, cudaStreamNonBlocking);
        cudaStreamCreateWithFlags(&sGB, cudaStreamNonBlocking);
        cudaStreamCreateWithFlags(&sM2, cudaStreamNonBlocking);
        cudaEventCreateWithFlags(&evFork, cudaEventDisableTiming);
        cudaEventCreateWithFlags(&evPre, cudaEventDisableTiming);
        cudaEventCreateWithFlags(&evCSR, cudaEventDisableTiming);
        cudaEventCreateWithFlags(&evEnd, cudaEventDisableTiming);
        for (int r = 0; r < RN; r++)
            cudaEventCreateWithFlags(&evG[r], cudaEventDisableTiming);
        cudaFuncSetAttribute(gemm_big_kernel,
                             cudaFuncAttributeMaxDynamicSharedMemorySize, SMEM_BIG);
        cudaFuncSetAttribute(gemm_dual_kernel,
                             cudaFuncAttributeMaxDynamicSharedMemorySize, SMEM_GEMM);
    }

    const int M = NN;
    int nodeBlocks = (NN * 32 + 255) / 256;   // warp per node
    cudaStream_t s0 = 0;  // capture-origin stream

    // --- preprocessing: rounding/transposes on s0; CSR build on sM2 ---
    round_tf32_kernel<<<4096, 256, 0, s0>>>((const float4*)x, (float4*)XR, NN * DD / 4);
    cudaEventRecord(evFork, s0);
    cudaStreamWaitEvent(sM2, evFork, 0);

    // sM2: CSR build with 3-phase parallel scan
    zero_int_kernel<<<1024, 256, 0, sM2>>>(tmp, 2 * RN * NN);
    hist_kernel<<<(RN * EE + 255) / 256, 256, 0, sM2>>>(ei, counts);
    blocksum_kernel<<<dim3(CHUNKS, RN), 256, 0, sM2>>>(counts, blksum);
    blkscan_kernel<<<RN, 32, 0, sM2>>>(blksum);
    chunkscan_kernel<<<dim3(CHUNKS, RN), 1024, 0, sM2>>>(counts, blksum, rowptr);
    fillcsr_kernel<<<(RN * EE + 255) / 256, 256, 0, sM2>>>(ei, rowptr, cursor, colidx);
    cudaEventRecord(evCSR, sM2);

    // s0: weight transposes
    transpose_w_kernel<<<dim3(24, 16, RN), dim3(32, 8), 0, s0>>>(Wl, Wr, WT);
    transpose_wb1_kernel<<<dim3(8, 4, RN), dim3(32, 8), 0, s0>>>(Wrel1, Wroot1, WB1);
    cudaEventRecord(evPre, s0);

    cudaStreamWaitEvent(sGA, evPre, 0);  // GEMMs need XR + WT
    cudaStreamWaitEvent(sGB, evPre, 0);
    cudaStreamWaitEvent(s0, evCSR, 0);   // parity-0 mains need CSR
    cudaStreamWaitEvent(sM2, evPre, 0);  // parity-1 mains need WB1

    for (int r = 0; r < RN; r++) {
        const int* rp = rowptr + r * (NN + 1);
        const int* ci = colidx + r * EE;
        int par = r & 1;
        float* XLR = scratch + OFF_XLR0 + (size_t)r * XLR_STRIDE;  // per-relation buffer
        cudaStream_t sP = par ? sM2 : s0;
        cudaStream_t sG = par ? sGB : sGA;   // GEMM stream by parity

        // --- GEMM for relation r: fully independent, no buffer-reuse deps ---
        gemm_big_kernel<<<dim3(2, (M + GBM - 1) / GBM), 512, SMEM_BIG, sG>>>(
            XR, WT + (size_t)r * 512 * DD, XLR, M);
        cudaEventRecord(evG[r], sG);

        // --- main chain for relation r on its parity stream ---
        cudaStreamWaitEvent(sP, evG[r], 0);

        gat_csr_kernel<<<nodeBlocks, 256, 0, sP>>>(XLR, rp, ci,
                                                   att + (size_t)r * HC,
                                                   bg + (size_t)r * HC, Hb[par]);

        // GraphConv 1 (tensor): P1 = h@Wrel1, H1 = h@Wroot1 + b1
        gemm_dual_kernel<<<dim3(1, (M + BM - 1) / BM), 256, SMEM_GEMM, sP>>>(
            Hb[par], WB1 + (size_t)r * 128 * HC, P1b[par], H1b[par],
            b1 + (size_t)r * OO, M);
        gather_csr64_kernel<<<nodeBlocks, 256, 0, sP>>>(P1b[par], rp, ci, H1b[par], OO, 1);

        // GraphConv 2 (SIMT, K=64) -> out[:, r, :]
        gemm64_dual_kernel<<<(M + 63) / 64, 256, 0, sP>>>(
            H1b[par], Wrel2 + (size_t)r * OO * OO, Wroot2 + (size_t)r * OO * OO,
            b2 + (size_t)r * OO, P2b[par], out + (size_t)r * OO, RN * OO, M, OO);
        gather_csr64_kernel<<<nodeBlocks, 256, 0, sP>>>(P2b[par], rp, ci,
                                                        out + (size_t)r * OO, RN * OO, 0);
    }

    // join parity-1 stream back into the capture-origin stream
    cudaEventRecord(evEnd, sM2);
    cudaStreamWaitEvent(s0, evEnd, 0);
}